// round 11
// baseline (speedup 1.0000x reference)
#include <cuda_runtime.h>
#include <stdint.h>

// out[b,i,j,:] = pe[clamp(128 + j - i, 0, 256), :]
// B=4, S=512, D=128, pe is [512,128] fp32 (rows 0..256 referenced).
//
// HBM-write-bound: 537 MB irreducible stores. Contiguous STG.128 with
// multiple rows per warp is the winning family; measured scan:
//   1 row/warp: DRAM 80.3%, 2: 82.1%, 4: 83.5% (monotone).
// This variant: EIGHT consecutive rows per warp (4 KB contiguous),
// 8 independent STG.128 in flight, index math amortized 8x.
// j0 % 8 == 0 so all 8 rows share one i; rels are rel0..rel0+7.
// Grid exactly covers 131,072 warps -> no bounds check.

__global__ __launch_bounds__(256) void relpos_kernel8(
    const float4* __restrict__ pe,   // [512][32] float4
    float4* __restrict__ out)        // [B*S*S][32] float4
{
    unsigned gtid = blockIdx.x * 256u + threadIdx.x;
    unsigned grp  = gtid >> 5;       // 8-row group index
    unsigned lane = gtid & 31;

    unsigned row0 = grp << 3;        // j0 multiple of 8 -> same i for all 8
    int j0 = row0 & 511;
    int i  = (row0 >> 9) & 511;

    int rel = 128 + j0 - i;

    float4 v[8];
    #pragma unroll
    for (int t = 0; t < 8; ++t) {
        int r = rel + t;
        r = r < 0 ? 0 : (r > 256 ? 256 : r);
        v[t] = __ldg(pe + r * 32 + lane);   // L1-resident table
    }

    float4* dst = out + (size_t)grp * 256 + lane;
    #pragma unroll
    for (int t = 0; t < 8; ++t)
        __stcs(dst + t * 32, v[t]);         // 8 contiguous 512B row writes
}

extern "C" void kernel_launch(void* const* d_in, const int* in_sizes, int n_in,
                              void* d_out, int out_size)
{
    // d_in[0] = x (int32 [B,512], shape-only), d_in[1] = pe (float32 [512,128])
    const float4* pe = (const float4*)d_in[1];
    float4* out = (float4*)d_out;

    int n_rows = out_size >> 7;                 // B*S*S = 1,048,576
    int grid = (n_rows / 8 * 32) / 256;         // exact: 16,384

    relpos_kernel8<<<grid, 256>>>(pe, out);
}

// round 12
// speedup vs baseline: 1.0022x; 1.0022x over previous
#include <cuda_runtime.h>
#include <stdint.h>

// out[b,i,j,:] = pe[clamp(128 + j - i, 0, 256), :]
// B=4, S=512, D=128, pe is [512,128] fp32 (rows 0..256 referenced).
//
// HBM-write-bound: 537 MB irreducible stores. Winning family: contiguous
// STG.128, multiple rows per warp. Measured rows/warp scan:
//   1: DRAM 80.3% | 2: 82.1% | 4: 83.5% (peak) | 8: 83.2%
// -> 4 consecutive rows per warp (2 KB contiguous), 4 independent STG.128
// in flight. This round: block=512 (halves block count / per-block drain
// overhead; adjacent warps cover contiguous 4 KB+ spans).
// Grid exactly covers 262,144 warps -> no bounds check.

__global__ __launch_bounds__(512) void relpos_kernel4b(
    const float4* __restrict__ pe,   // [512][32] float4
    float4* __restrict__ out)        // [B*S*S][32] float4
{
    unsigned gtid = blockIdx.x * 512u + threadIdx.x;
    unsigned quad = gtid >> 5;       // 4-row group index
    unsigned lane = gtid & 31;

    unsigned row0 = quad << 2;       // j0 multiple of 4 -> same i for all 4
    int j0 = row0 & 511;
    int i  = (row0 >> 9) & 511;

    int rel = 128 + j0 - i;

    float4 v[4];
    #pragma unroll
    for (int t = 0; t < 4; ++t) {
        int r = rel + t;
        r = r < 0 ? 0 : (r > 256 ? 256 : r);
        v[t] = __ldg(pe + r * 32 + lane);   // L1-resident table
    }

    float4* dst = out + (size_t)quad * 128 + lane;
    #pragma unroll
    for (int t = 0; t < 4; ++t)
        __stcs(dst + t * 32, v[t]);         // 4 contiguous 512B row writes
}

extern "C" void kernel_launch(void* const* d_in, const int* in_sizes, int n_in,
                              void* d_out, int out_size)
{
    // d_in[0] = x (int32 [B,512], shape-only), d_in[1] = pe (float32 [512,128])
    const float4* pe = (const float4*)d_in[1];
    float4* out = (float4*)d_out;

    int n_rows = out_size >> 7;                 // B*S*S = 1,048,576
    int grid = (n_rows / 4 * 32) / 512;         // exact: 16,384

    relpos_kernel4b<<<grid, 512>>>(pe, out);
}

// round 13
// speedup vs baseline: 1.0048x; 1.0026x over previous
#include <cuda_runtime.h>
#include <stdint.h>

// out[b,i,j,:] = pe[clamp(128 + j - i, 0, 256), :]
// B=4, S=512, D=128, pe is [512,128] fp32 (rows 0..256 referenced).
//
// HBM-write-bound: 537 MB irreducible stores (~93% of HBM3e write spec
// achieved). Winning family: contiguous STG.128, 4 consecutive rows per
// warp (2 KB), 4 independent stores in flight. Measured scans:
//   rows/warp: 1: 80.3% | 2: 82.1% | 4: 83.5% (peak) | 8: 83.2%  (DRAM%)
//   block:     256: 83.5% / 72.1us | 512: 83.8% / 71.8us (ncu dur)
// This round: block=1024 (8192 blocks, 128 KB contiguous per block).
// Grid exactly covers 262,144 warps -> no bounds check.

__global__ __launch_bounds__(1024) void relpos_kernel4c(
    const float4* __restrict__ pe,   // [512][32] float4
    float4* __restrict__ out)        // [B*S*S][32] float4
{
    unsigned gtid = blockIdx.x * 1024u + threadIdx.x;
    unsigned quad = gtid >> 5;       // 4-row group index
    unsigned lane = gtid & 31;

    unsigned row0 = quad << 2;       // j0 multiple of 4 -> same i for all 4
    int j0 = row0 & 511;
    int i  = (row0 >> 9) & 511;

    int rel = 128 + j0 - i;

    float4 v[4];
    #pragma unroll
    for (int t = 0; t < 4; ++t) {
        int r = rel + t;
        r = r < 0 ? 0 : (r > 256 ? 256 : r);
        v[t] = __ldg(pe + r * 32 + lane);   // L1-resident table
    }

    float4* dst = out + (size_t)quad * 128 + lane;
    #pragma unroll
    for (int t = 0; t < 4; ++t)
        __stcs(dst + t * 32, v[t]);         // 4 contiguous 512B row writes
}

extern "C" void kernel_launch(void* const* d_in, const int* in_sizes, int n_in,
                              void* d_out, int out_size)
{
    // d_in[0] = x (int32 [B,512], shape-only), d_in[1] = pe (float32 [512,128])
    const float4* pe = (const float4*)d_in[1];
    float4* out = (float4*)d_out;

    int n_rows = out_size >> 7;                 // B*S*S = 1,048,576
    int grid = (n_rows / 4 * 32) / 1024;        // exact: 8,192

    relpos_kernel4c<<<grid, 1024>>>(pe, out);
}